// round 13
// baseline (speedup 1.0000x reference)
#include <cuda_runtime.h>

#define EPSF 1e-8f
#define LNK   16
#define DST   255
#define TUN   1020
#define NCH   8
#define PAIRS 28
#define ROWS  56
#define SSTR  58            // words per group slot (28 pairs*2 + 2 pad)
#define PLW   (32*SSTR)     // 1856 words per plane
#define BUFDW (4*PLW)       // 7424 product data words
#define BUFW  (BUFDW+64)    // + zero region
#define ZBYTE (BUFDW*4)     // 29696, fits u16
#define SCHW  144
#define THR   512

#define RAT_SLOTW 7168      // 56 rows * 128 words
#define DEM_SLOTW 1792      // 56 rows * 32 words
// smem word map
#define W_RAWD  (2*RAT_SLOTW)            // 14336
#define W_PROD  (W_RAWD + 2*DEM_SLOTW)   // 17920
#define W_SCHED (W_PROD + BUFW)          // 25408
#define W_OFF   (W_SCHED + (NCH*SCHW)/2)
#define W_CUR   (W_OFF + NCH*17)
#define W_NL    (W_CUR + NCH*17)
#define W_INV   (W_NL + ROWS*17)
#define W_LOSS  (W_INV + 16)
#define W_FIN   (W_LOSS + 16)
#define W_LAST  (W_FIN + THR)
#define W_TOTAL (W_LAST + 1)

__device__ float    g_partials[512];
__device__ unsigned g_count;

__device__ __forceinline__ unsigned long long lds64(unsigned a) {
    unsigned long long v;
    asm volatile("ld.shared.b64 %0, [%1];" : "=l"(v) : "r"(a));
    return v;
}
__device__ __forceinline__ unsigned long long addx2(unsigned long long a,
                                                    unsigned long long b) {
    unsigned long long r;
    asm("add.rn.f32x2 %0, %1, %2;" : "=l"(r) : "l"(a), "l"(b));
    return r;
}
#define CP_COMMIT() asm volatile("cp.async.commit_group;")
#define CP_WAIT(n)  asm volatile("cp.async.wait_group %0;" :: "n"(n))

__global__ __launch_bounds__(THR, 2) void loss_kernel(
    const float* __restrict__ pred,   // [B,1020]
    const float* __restrict__ dem,    // [B,255]
    const float* __restrict__ clu,    // [B,16]
    const float* __restrict__ caps,   // [16]
    const int*   __restrict__ t2l,    // [1020]
    float* __restrict__ out,
    int B, int nb, float invB)
{
    extern __shared__ float smf[];
    unsigned short* s_sched = (unsigned short*)(smf + W_SCHED);
    int*   s_off  = (int*)(smf + W_OFF);
    int*   s_cur  = (int*)(smf + W_CUR);
    float* s_nl   = smf + W_NL;
    float* s_inv  = smf + W_INV;
    float* s_loss = smf + W_LOSS;
    float* s_fin  = smf + W_FIN;
    int*   s_last = (int*)(smf + W_LAST);

    const int tid  = threadIdx.x;
    const int warp = tid >> 5;
    const int lane = tid & 31;
    const int base = blockIdx.x * ROWS;
    const unsigned sm32 = (unsigned)__cvta_generic_to_shared(smf);

    unsigned long long acc0 = 0ull, acc1 = 0ull;

    // issue this warp's cp.asyncs for chunk ch into raw slot s; one group
    #define CPLOAD(ch, s)                                                         \
    {                                                                             \
        _Pragma("unroll")                                                         \
        for (int u = 0; u < 2; ++u) {                                             \
            const int pr = warp + 16 * u;                                         \
            if (pr < PAIRS) {                                                     \
                _Pragma("unroll")                                                 \
                for (int v = 0; v < 2; ++v) {                                     \
                    const int row  = pr + PAIRS * v;                              \
                    const int grow = base + row;                                  \
                    const bool rv  = (grow < B);                                  \
                    if (rv && ((ch) < 7 || lane < 31)) {                          \
                        const unsigned d = sm32 + (unsigned)(((s) * RAT_SLOTW     \
                                         + row * 128 + lane * 4) * 4);            \
                        const char* g = (const char*)pred + (size_t)grow * 4080   \
                                      + (ch) * 512 + lane * 16;                   \
                        asm volatile("cp.async.cg.shared.global [%0], [%1], 16;"  \
                                     :: "r"(d), "l"(g));                          \
                    }                                                             \
                    if (rv && ((ch) * 32 + lane) < DST) {                         \
                        const unsigned d = sm32 + (unsigned)((W_RAWD              \
                                         + (s) * DEM_SLOTW + row * 32 + lane) * 4);\
                        const char* g = (const char*)dem + (size_t)grow * 1020    \
                                      + (ch) * 128 + lane * 4;                    \
                        asm volatile("cp.async.ca.shared.global [%0], [%1], 4;"   \
                                     :: "r"(d), "l"(g));                          \
                    }                                                             \
                }                                                                 \
            }                                                                     \
        }                                                                         \
        CP_COMMIT();                                                              \
    }

    // transpose this warp's rows from raw slot s into the product buffer
    #define TRANS(s)                                                              \
    {                                                                             \
        _Pragma("unroll")                                                         \
        for (int u = 0; u < 2; ++u) {                                             \
            const int pr = warp + 16 * u;                                         \
            if (pr < PAIRS) {                                                     \
                const float4 rv0 = ((const float4*)(smf + (s) * RAT_SLOTW + pr * 128))[lane];           \
                const float4 rv1 = ((const float4*)(smf + (s) * RAT_SLOTW + (pr + PAIRS) * 128))[lane]; \
                const float d0 = smf[W_RAWD + (s) * DEM_SLOTW + pr * 32 + lane];          \
                const float d1 = smf[W_RAWD + (s) * DEM_SLOTW + (pr + PAIRS) * 32 + lane];\
                float* bp = smf + W_PROD;                                         \
                const int wb = lane * SSTR + pr * 2;                              \
                ((float2*)bp)[(0 * PLW + wb) >> 1] = make_float2(rv0.x * d0, rv1.x * d1); \
                ((float2*)bp)[(1 * PLW + wb) >> 1] = make_float2(rv0.y * d0, rv1.y * d1); \
                ((float2*)bp)[(2 * PLW + wb) >> 1] = make_float2(rv0.z * d0, rv1.z * d1); \
                ((float2*)bp)[(3 * PLW + wb) >> 1] = make_float2(rv0.w * d0, rv1.w * d1); \
            }                                                                     \
        }                                                                         \
    }

    #define GATHER(ch)                                                            \
    {                                                                             \
        const unsigned lbase = sm32 + (unsigned)(W_PROD * 4) + (unsigned)(lane << 3); \
        const unsigned short* sc = s_sched + (ch) * SCHW;                         \
        int k = s_off[(ch) * 17 + warp];                                          \
        const int hi = s_off[(ch) * 17 + warp + 1];                               \
        _Pragma("unroll 2")                                                       \
        for (; k < hi; k += 2) {                                                  \
            const unsigned o0 = sc[k];                                            \
            const unsigned o1 = sc[k + 1];                                        \
            acc0 = addx2(acc0, lds64(lbase + o0));                                \
            acc1 = addx2(acc1, lds64(lbase + o1));                                \
        }                                                                         \
    }

    #define ITER(c)                                                               \
    {                                                                             \
        if ((c) < 7) { CP_WAIT(1); } else { CP_WAIT(0); }  /* own chunk c done */ \
        TRANS((c) & 1);                                                           \
        if ((c) + 2 < NCH) CPLOAD((c) + 2, (c) & 1);       /* refill freed slot */\
        __syncthreads();                                   /* products visible */ \
        GATHER(c);                                                                \
        __syncthreads();                                   /* products reusable */\
    }

    // ---------------- prologue ----------------------------------------------
    // zero raw ring (determinism for invalid rows) — must precede cp.async
    for (int i = tid; i < W_PROD; i += THR) smf[i] = 0.0f;
    __syncthreads();

    CPLOAD(0, 0);
    CPLOAD(1, 1);

    // schedule build: warp c (<8) sorts chunk c by bin (overlaps cp.async)
    if (warp < 8) {
        const int c = warp;
        int* cur = s_cur + c * 17;
        int* off = s_off + c * 17;
        if (lane < 17) cur[lane] = 0;
        int bins[4];
        #pragma unroll
        for (int q = 0; q < 4; ++q) {
            const int t = c * 128 + q * 32 + lane;
            bins[q] = (t < TUN) ? t2l[t] : 16;
        }
        __syncwarp();
        #pragma unroll
        for (int q = 0; q < 4; ++q) {
            const unsigned peers = __match_any_sync(0xffffffffu, bins[q]);
            const int rank = __popc(peers & ((1u << lane) - 1u));
            if (rank == 0) cur[bins[q]] += __popc(peers);
            __syncwarp();
        }
        if (lane < 17) {
            int o = 0;
            for (int i = 0; i < lane; ++i) o += (cur[i] + 1) & ~1;
            off[lane] = o;
        }
        __syncwarp();
        for (int i = lane; i < SCHW; i += 32)
            s_sched[c * SCHW + i] = (unsigned short)ZBYTE;
        if (lane < 17) cur[lane] = off[lane];
        __syncwarp();
        #pragma unroll
        for (int q = 0; q < 4; ++q) {
            const unsigned peers = __match_any_sync(0xffffffffu, bins[q]);
            const int rank = __popc(peers & ((1u << lane) - 1u));
            const int bse  = cur[bins[q]];
            __syncwarp();
            if (rank == 0) cur[bins[q]] = bse + __popc(peers);
            __syncwarp();
            if (bins[q] < 16) {
                const int tl = q * 32 + lane;
                const unsigned o = (unsigned)(tl & 3) * (PLW * 4)
                                 + (unsigned)(tl >> 2) * (SSTR * 4);
                s_sched[c * SCHW + bse + rank] = (unsigned short)o;
            }
        }
    }
    // product zero region
    if (tid >= 256 && tid < 320) smf[W_PROD + BUFDW + (tid - 256)] = 0.0f;
    if (tid < LNK) s_inv[tid] = 1.0f / (caps[tid] + EPSF);
    __syncthreads();   // schedule + zero region visible

    // ---------------- fully unrolled pipeline --------------------------------
    ITER(0); ITER(1); ITER(2); ITER(3);
    ITER(4); ITER(5); ITER(6); ITER(7);

    // ---------------- stats ---------------------------------------------------
    {
        const unsigned long long t = addx2(acc0, acc1);
        const float lo = __uint_as_float((unsigned)(t & 0xffffffffull));
        const float hi = __uint_as_float((unsigned)(t >> 32));
        if (lane < PAIRS) {
            s_nl[lane * 17 + warp] = lo;
            s_nl[(lane + PAIRS) * 17 + warp] = hi;
        }
    }
    __syncthreads();

    float lsum = 0.0f;
    #pragma unroll
    for (int p = 0; p < 2; ++p) {
        const int rid = p * 32 + (warp << 1) + (lane >> 4);
        const int j = lane & 15;
        const int brow = base + rid;
        const bool rok = (rid < ROWS) && (brow < B);
        const float u   = rok ? s_nl[rid * 17 + j] * s_inv[j] : 0.0f;
        const float cur = rok ? clu[(size_t)brow * LNK + j] : 0.0f;

        float smn = u;
        #pragma unroll
        for (int off = 1; off < 16; off <<= 1)
            smn += __shfl_xor_sync(0xffffffffu, smn, off);
        const float mean = smn * (1.0f / 16.0f);

        const float dv = u - mean;
        float q2  = dv * dv;
        float dot = u * cur;
        float mx  = u;
        #pragma unroll
        for (int off = 1; off < 16; off <<= 1) {
            q2  += __shfl_xor_sync(0xffffffffu, q2, off);
            dot += __shfl_xor_sync(0xffffffffu, dot, off);
            mx   = fmaxf(mx, __shfl_xor_sync(0xffffffffu, mx, off));
        }
        if (j == 0 && rok)
            lsum += 0.3f * (q2 * (1.0f / 15.0f)) + 0.5f * dot + 0.2f * mx;
    }
    lsum += __shfl_xor_sync(0xffffffffu, lsum, 16);
    if (lane == 0) s_loss[warp] = lsum;
    __syncthreads();

    // ---------------- deterministic single-launch reduction -------------------
    if (tid == 0) {
        float t = 0.0f;
        #pragma unroll
        for (int w = 0; w < 16; ++w) t += s_loss[w];
        g_partials[blockIdx.x] = t;
        __threadfence();
        const unsigned old = atomicAdd(&g_count, 1u);
        *s_last = (old == (unsigned)(nb - 1));
    }
    __syncthreads();

    if (*s_last) {
        float v = 0.0f;
        for (int i = tid; i < nb; i += THR) v += __ldcg(&g_partials[i]);
        s_fin[tid] = v;
        __syncthreads();
        #pragma unroll
        for (int st = 256; st > 0; st >>= 1) {
            if (tid < st) s_fin[tid] += s_fin[tid + st];
            __syncthreads();
        }
        if (tid == 0) {
            out[0] = s_fin[0] * invB;
            g_count = 0;
        }
    }
}

extern "C" void kernel_launch(void* const* d_in, const int* in_sizes, int n_in,
                              void* d_out, int out_size)
{
    const float* pred = (const float*)d_in[0];
    const float* dem  = (const float*)d_in[1];
    const float* clu  = (const float*)d_in[2];
    const float* caps = (const float*)d_in[3];
    const int*   t2l  = (const int*)d_in[4];
    float* out = (float*)d_out;

    const int B  = in_sizes[0] / TUN;           // 16384
    int nb = (B + ROWS - 1) / ROWS;             // 293
    if (nb > 512) nb = 512;

    const int smem_bytes = W_TOTAL * 4;         // ~111 KB
    cudaFuncSetAttribute(loss_kernel,
                         cudaFuncAttributeMaxDynamicSharedMemorySize, smem_bytes);
    loss_kernel<<<nb, THR, smem_bytes>>>(pred, dem, clu, caps, t2l, out,
                                         B, nb, 1.0f / (float)B);
}

// round 14
// speedup vs baseline: 1.0889x; 1.0889x over previous
#include <cuda_runtime.h>

#define EPSF 1e-8f
#define LNK   16
#define DST   255
#define TUN   1020
#define NCH   8
#define PAIRS 28
#define ROWS  56
#define SSTR  58            // words per group slot (28 pairs*2 + 2 pad)
#define PLW   (32*SSTR)     // 1856 words per plane
#define BUFDW (4*PLW)       // 7424 product data words
#define BUFW  (BUFDW+64)    // + zero region
#define ZBYTE (BUFDW*4)     // 29696, fits u16
#define SCHW  144
#define THR   512

#define RAT_SLOTW 7168      // 56 rows * 128 words
#define DEM_SLOTW 1792      // 56 rows * 32 words
// smem word map
#define W_RAW   0
#define W_DEMR  (2*RAT_SLOTW)             // 14336
#define W_PROD  (W_DEMR + 2*DEM_SLOTW)    // 17920
#define W_SCHED (W_PROD + BUFW)           // 25408
#define W_OFF   (W_SCHED + (NCH*SCHW)/2)  // 25984
#define W_CUR   (W_OFF + NCH*17)
#define W_NL    (W_CUR + NCH*17)
#define W_INV   (W_NL + ROWS*17)
#define W_LOSS  (W_INV + 16)
#define W_FIN   (W_LOSS + 16)
#define W_LAST  (W_FIN + THR)
#define W_MBAR  ((W_LAST + 2) & ~1)       // 8B aligned
#define W_TOTAL (W_MBAR + 4)

__device__ float    g_partials[512];
__device__ unsigned g_count;

__device__ __forceinline__ unsigned long long lds64(unsigned a) {
    unsigned long long v;
    asm volatile("ld.shared.b64 %0, [%1];" : "=l"(v) : "r"(a));
    return v;
}
__device__ __forceinline__ unsigned long long addx2(unsigned long long a,
                                                    unsigned long long b) {
    unsigned long long r;
    asm("add.rn.f32x2 %0, %1, %2;" : "=l"(r) : "l"(a), "l"(b));
    return r;
}
#define CP_COMMIT() asm volatile("cp.async.commit_group;")
#define CP_WAIT(n)  asm volatile("cp.async.wait_group %0;" :: "n"(n))

__device__ __forceinline__ void bulk_g2s(unsigned dst, const void* src,
                                         unsigned bytes, unsigned mbar) {
    asm volatile(
        "cp.async.bulk.shared::cluster.global.mbarrier::complete_tx::bytes "
        "[%0], [%1], %2, [%3];"
        :: "r"(dst), "l"(src), "r"(bytes), "r"(mbar) : "memory");
}
__device__ __forceinline__ void mbar_init(unsigned a) {
    asm volatile("mbarrier.init.shared.b64 [%0], 1;" :: "r"(a) : "memory");
}
__device__ __forceinline__ void mbar_expect(unsigned a, unsigned bytes) {
    asm volatile("mbarrier.arrive.expect_tx.shared.b64 _, [%0], %1;"
                 :: "r"(a), "r"(bytes) : "memory");
}
__device__ __forceinline__ void mbar_wait(unsigned a, unsigned par) {
    unsigned done = 0;
    while (!done) {
        asm volatile(
            "{\n\t.reg .pred p;\n\t"
            "mbarrier.try_wait.parity.acquire.cta.shared::cta.b64 p, [%1], %2;\n\t"
            "selp.b32 %0, 1, 0, p;\n\t}"
            : "=r"(done) : "r"(a), "r"(par) : "memory");
    }
}

__global__ __launch_bounds__(THR, 2) void loss_kernel(
    const float* __restrict__ pred,   // [B,1020]
    const float* __restrict__ dem,    // [B,255]
    const float* __restrict__ clu,    // [B,16]
    const float* __restrict__ caps,   // [16]
    const int*   __restrict__ t2l,    // [1020]
    float* __restrict__ out,
    int B, int nb, float invB)
{
    extern __shared__ float smf[];
    unsigned short* s_sched = (unsigned short*)(smf + W_SCHED);
    int*   s_off  = (int*)(smf + W_OFF);
    int*   s_cur  = (int*)(smf + W_CUR);
    float* s_nl   = smf + W_NL;
    float* s_inv  = smf + W_INV;
    float* s_loss = smf + W_LOSS;
    float* s_fin  = smf + W_FIN;
    int*   s_last = (int*)(smf + W_LAST);

    const int tid  = threadIdx.x;
    const int warp = tid >> 5;
    const int lane = tid & 31;
    const int base = blockIdx.x * ROWS;
    const unsigned sm32 = (unsigned)__cvta_generic_to_shared(smf);
    const int nv = min(ROWS, B - base);            // valid rows this block

    unsigned long long acc0 = 0ull, acc1 = 0ull;

    // ---- bulk TMA-path issue for pred chunk ch into raw slot ch&1 ----------
    #define TMAISSUE(ch)                                                          \
    {                                                                             \
        const unsigned bytes = ((ch) == 7) ? 496u : 512u;                         \
        if (tid == 0)                                                             \
            mbar_expect(sm32 + (unsigned)((W_MBAR + 2 * ((ch) & 1)) * 4),         \
                        (unsigned)nv * bytes);                                    \
        if (tid < nv) {                                                           \
            const unsigned dst = sm32 + (unsigned)(((((ch) & 1) * RAT_SLOTW)      \
                               + tid * 128) * 4);                                 \
            const char* src = (const char*)pred + (size_t)(base + tid) * 4080     \
                            + (ch) * 512;                                         \
            bulk_g2s(dst, src, bytes,                                             \
                     sm32 + (unsigned)((W_MBAR + 2 * ((ch) & 1)) * 4));           \
        }                                                                         \
    }

    // ---- demands via tiny cp.async (each warp loads its own rows) ----------
    #define DEMLOAD(ch)                                                           \
    {                                                                             \
        _Pragma("unroll")                                                         \
        for (int u = 0; u < 2; ++u) {                                             \
            const int pr = warp + 16 * u;                                         \
            if (pr < PAIRS) {                                                     \
                _Pragma("unroll")                                                 \
                for (int v = 0; v < 2; ++v) {                                     \
                    const int row  = pr + PAIRS * v;                              \
                    const int grow = base + row;                                  \
                    if (grow < B && ((ch) * 32 + lane) < DST) {                   \
                        const unsigned d = sm32 + (unsigned)((W_DEMR              \
                                         + ((ch) & 1) * DEM_SLOTW                 \
                                         + row * 32 + lane) * 4);                 \
                        const char* g = (const char*)dem + (size_t)grow * 1020    \
                                      + (ch) * 128 + lane * 4;                    \
                        asm volatile("cp.async.ca.shared.global [%0], [%1], 4;"   \
                                     :: "r"(d), "l"(g));                          \
                    }                                                             \
                }                                                                 \
            }                                                                     \
        }                                                                         \
    }

    #define TRANS(s)                                                              \
    {                                                                             \
        _Pragma("unroll")                                                         \
        for (int u = 0; u < 2; ++u) {                                             \
            const int pr = warp + 16 * u;                                         \
            if (pr < PAIRS) {                                                     \
                const float4 rv0 = ((const float4*)(smf + (s) * RAT_SLOTW + pr * 128))[lane];           \
                const float4 rv1 = ((const float4*)(smf + (s) * RAT_SLOTW + (pr + PAIRS) * 128))[lane]; \
                const float d0 = smf[W_DEMR + (s) * DEM_SLOTW + pr * 32 + lane];          \
                const float d1 = smf[W_DEMR + (s) * DEM_SLOTW + (pr + PAIRS) * 32 + lane];\
                float* bp = smf + W_PROD;                                         \
                const int wb = lane * SSTR + pr * 2;                              \
                ((float2*)bp)[(0 * PLW + wb) >> 1] = make_float2(rv0.x * d0, rv1.x * d1); \
                ((float2*)bp)[(1 * PLW + wb) >> 1] = make_float2(rv0.y * d0, rv1.y * d1); \
                ((float2*)bp)[(2 * PLW + wb) >> 1] = make_float2(rv0.z * d0, rv1.z * d1); \
                ((float2*)bp)[(3 * PLW + wb) >> 1] = make_float2(rv0.w * d0, rv1.w * d1); \
            }                                                                     \
        }                                                                         \
    }

    #define GATHER(ch)                                                            \
    {                                                                             \
        const unsigned lbase = sm32 + (unsigned)(W_PROD * 4) + (unsigned)(lane << 3); \
        const unsigned short* sc = s_sched + (ch) * SCHW;                         \
        int k = s_off[(ch) * 17 + warp];                                          \
        const int hi = s_off[(ch) * 17 + warp + 1];                               \
        _Pragma("unroll 2")                                                       \
        for (; k < hi; k += 2) {                                                  \
            const unsigned o0 = sc[k];                                            \
            const unsigned o1 = sc[k + 1];                                        \
            acc0 = addx2(acc0, lds64(lbase + o0));                                \
            acc1 = addx2(acc1, lds64(lbase + o1));                                \
        }                                                                         \
    }

    // parity of chunk c on its slot = (c>>1)&1 (2-slot ring)
    #define ITER(c)                                                               \
    {                                                                             \
        mbar_wait(sm32 + (unsigned)((W_MBAR + 2 * ((c) & 1)) * 4),                \
                  (unsigned)(((c) >> 1) & 1));                                    \
        CP_WAIT(1);                                    /* dem(c) landed */        \
        TRANS((c) & 1);                                                           \
        __syncthreads();                               /* raw slot consumed */    \
        if ((c) + 2 < NCH) { TMAISSUE((c) + 2); DEMLOAD((c) + 2); }               \
        CP_COMMIT();                                   /* uniform group count */  \
        GATHER(c);                                                                \
        __syncthreads();                               /* products reusable */    \
    }

    // ---------------- prologue ----------------------------------------------
    if (tid == 0) {
        mbar_init(sm32 + (unsigned)(W_MBAR * 4));
        mbar_init(sm32 + (unsigned)((W_MBAR + 2) * 4));
    }
    __syncthreads();                                   // mbars visible

    TMAISSUE(0); DEMLOAD(0); CP_COMMIT();
    TMAISSUE(1); DEMLOAD(1); CP_COMMIT();

    // schedule build: warp c (<8) sorts chunk c by bin (overlaps loads)
    if (warp < 8) {
        const int c = warp;
        int* cur = s_cur + c * 17;
        int* off = s_off + c * 17;
        if (lane < 17) cur[lane] = 0;
        int bins[4];
        #pragma unroll
        for (int q = 0; q < 4; ++q) {
            const int t = c * 128 + q * 32 + lane;
            bins[q] = (t < TUN) ? t2l[t] : 16;
        }
        __syncwarp();
        #pragma unroll
        for (int q = 0; q < 4; ++q) {
            const unsigned peers = __match_any_sync(0xffffffffu, bins[q]);
            const int rank = __popc(peers & ((1u << lane) - 1u));
            if (rank == 0) cur[bins[q]] += __popc(peers);
            __syncwarp();
        }
        if (lane < 17) {
            int o = 0;
            for (int i = 0; i < lane; ++i) o += (cur[i] + 1) & ~1;
            off[lane] = o;
        }
        __syncwarp();
        for (int i = lane; i < SCHW; i += 32)
            s_sched[c * SCHW + i] = (unsigned short)ZBYTE;
        if (lane < 17) cur[lane] = off[lane];
        __syncwarp();
        #pragma unroll
        for (int q = 0; q < 4; ++q) {
            const unsigned peers = __match_any_sync(0xffffffffu, bins[q]);
            const int rank = __popc(peers & ((1u << lane) - 1u));
            const int bse  = cur[bins[q]];
            __syncwarp();
            if (rank == 0) cur[bins[q]] = bse + __popc(peers);
            __syncwarp();
            if (bins[q] < 16) {
                const int tl = q * 32 + lane;
                const unsigned o = (unsigned)(tl & 3) * (PLW * 4)
                                 + (unsigned)(tl >> 2) * (SSTR * 4);
                s_sched[c * SCHW + bse + rank] = (unsigned short)o;
            }
        }
    }
    if (tid >= 256 && tid < 320) smf[W_PROD + BUFDW + (tid - 256)] = 0.0f;
    if (tid < LNK) s_inv[tid] = 1.0f / (caps[tid] + EPSF);
    __syncthreads();                                   // schedule visible

    // ---------------- fully unrolled pipeline --------------------------------
    ITER(0); ITER(1); ITER(2); ITER(3);
    ITER(4); ITER(5); ITER(6); ITER(7);

    // ---------------- stats ---------------------------------------------------
    {
        const unsigned long long t = addx2(acc0, acc1);
        const float lo = __uint_as_float((unsigned)(t & 0xffffffffull));
        const float hi = __uint_as_float((unsigned)(t >> 32));
        if (lane < PAIRS) {
            s_nl[lane * 17 + warp] = lo;
            s_nl[(lane + PAIRS) * 17 + warp] = hi;
        }
    }
    __syncthreads();

    float lsum = 0.0f;
    #pragma unroll
    for (int p = 0; p < 2; ++p) {
        const int rid = p * 32 + (warp << 1) + (lane >> 4);
        const int j = lane & 15;
        const int brow = base + rid;
        const bool rok = (rid < ROWS) && (brow < B);
        const float u   = rok ? s_nl[rid * 17 + j] * s_inv[j] : 0.0f;
        const float cur = rok ? clu[(size_t)brow * LNK + j] : 0.0f;

        float smn = u;
        #pragma unroll
        for (int off = 1; off < 16; off <<= 1)
            smn += __shfl_xor_sync(0xffffffffu, smn, off);
        const float mean = smn * (1.0f / 16.0f);

        const float dv = u - mean;
        float q2  = dv * dv;
        float dot = u * cur;
        float mx  = u;
        #pragma unroll
        for (int off = 1; off < 16; off <<= 1) {
            q2  += __shfl_xor_sync(0xffffffffu, q2, off);
            dot += __shfl_xor_sync(0xffffffffu, dot, off);
            mx   = fmaxf(mx, __shfl_xor_sync(0xffffffffu, mx, off));
        }
        if (j == 0 && rok)
            lsum += 0.3f * (q2 * (1.0f / 15.0f)) + 0.5f * dot + 0.2f * mx;
    }
    lsum += __shfl_xor_sync(0xffffffffu, lsum, 16);
    if (lane == 0) s_loss[warp] = lsum;
    __syncthreads();

    // ---------------- deterministic single-launch reduction -------------------
    if (tid == 0) {
        float t = 0.0f;
        #pragma unroll
        for (int w = 0; w < 16; ++w) t += s_loss[w];
        g_partials[blockIdx.x] = t;
        __threadfence();
        const unsigned old = atomicAdd(&g_count, 1u);
        *s_last = (old == (unsigned)(nb - 1));
    }
    __syncthreads();

    if (*s_last) {
        float v = 0.0f;
        for (int i = tid; i < nb; i += THR) v += __ldcg(&g_partials[i]);
        s_fin[tid] = v;
        __syncthreads();
        #pragma unroll
        for (int st = 256; st > 0; st >>= 1) {
            if (tid < st) s_fin[tid] += s_fin[tid + st];
            __syncthreads();
        }
        if (tid == 0) {
            out[0] = s_fin[0] * invB;
            g_count = 0;
        }
    }
}

extern "C" void kernel_launch(void* const* d_in, const int* in_sizes, int n_in,
                              void* d_out, int out_size)
{
    const float* pred = (const float*)d_in[0];
    const float* dem  = (const float*)d_in[1];
    const float* clu  = (const float*)d_in[2];
    const float* caps = (const float*)d_in[3];
    const int*   t2l  = (const int*)d_in[4];
    float* out = (float*)d_out;

    const int B  = in_sizes[0] / TUN;           // 16384
    int nb = (B + ROWS - 1) / ROWS;             // 293
    if (nb > 512) nb = 512;

    const int smem_bytes = W_TOTAL * 4;         // ~111 KB
    cudaFuncSetAttribute(loss_kernel,
                         cudaFuncAttributeMaxDynamicSharedMemorySize, smem_bytes);
    loss_kernel<<<nb, THR, smem_bytes>>>(pred, dem, clu, caps, t2l, out,
                                         B, nb, 1.0f / (float)B);
}